// round 15
// baseline (speedup 1.0000x reference)
#include <cuda_runtime.h>

#define NB       16
#define NFRAMES  1024
#define BINS     513
#define WINL     1024
#define HOP      256
#define OUTLEN   262912                  // (1024-1)*256 + 1024 = 64*4096 + 768
#define BLK      4096                    // core output samples per CTA
#define TAIL     768                     // tail spill samples per CTA
#define NCTAX    64                      // CTAs per batch row
#define NG       4                       // FFTs (frames) per CTA iteration
#define BUFSZ    576                     // padded float2 slots per FFT buffer (=288 float4)

// smem: bufA[NG][576] f2 | bufB[NG][576] f2 = 36KB -> 5 CTAs/SM fits (180KB < 228KB)
#define SMEM_BYTES (2*NG*BUFSZ*8)

// tail-spill strips: [batch][ctaX][768]  (static device scratch, 3.1MB)
__device__ float g_strip[NB * NCTAX * TAIL];

__device__ __forceinline__ float2 cmul(float2 a, float2 b) {
    return make_float2(a.x*b.x - a.y*b.y, a.x*b.y + a.y*b.x);
}
__device__ __forceinline__ float2 cadd(float2 a, float2 b){ return make_float2(a.x+b.x, a.y+b.y); }
__device__ __forceinline__ float2 csub(float2 a, float2 b){ return make_float2(a.x-b.x, a.y-b.y); }

// padded layouts (bank-conflict-free for this stage schedule)
__device__ __forceinline__ int P1(int e){ return e + (e >> 3); }        // max 574 < 576
__device__ __forceinline__ int P2(int e){ return e + ((e >> 6) << 3); } // max 567 < 576

// inverse radix-8 butterfly: y_k = sum_j x_j * e^{+2*pi*i*j*k/8}
__device__ __forceinline__ void bfly8_inv(const float2* x, float2* y) {
    float2 apc = cadd(x[0], x[4]), amc = csub(x[0], x[4]);
    float2 bpd = cadd(x[2], x[6]), bmd = csub(x[2], x[6]);
    float2 ib  = make_float2(-bmd.y, bmd.x);
    float2 A0 = cadd(apc, bpd), A2 = csub(apc, bpd);
    float2 A1 = cadd(amc, ib),  A3 = csub(amc, ib);
    float2 cpc = cadd(x[1], x[5]), cmc = csub(x[1], x[5]);
    float2 dpd = cadd(x[3], x[7]), dmd = csub(x[3], x[7]);
    float2 id  = make_float2(-dmd.y, dmd.x);
    float2 B0 = cadd(cpc, dpd), B2 = csub(cpc, dpd);
    float2 B1 = cadd(cmc, id),  B3 = csub(cmc, id);
    const float r = 0.70710678118654752f;
    float2 wB1  = make_float2(r*(B1.x - B1.y),  r*(B1.x + B1.y));   // w8^1 * B1
    float2 iB2  = make_float2(-B2.y, B2.x);                          // w8^2 * B2
    float2 w3B3 = make_float2(-r*(B3.x + B3.y), r*(B3.x - B3.y));   // w8^3 * B3
    y[0] = cadd(A0, B0);   y[4] = csub(A0, B0);
    y[1] = cadd(A1, wB1);  y[5] = csub(A1, wB1);
    y[2] = cadd(A2, iB2);  y[6] = csub(A2, iB2);
    y[3] = cadd(A3, w3B3); y[7] = csub(A3, w3B3);
}

__global__ void __launch_bounds__(256, 5) istft_k1(
    const float* __restrict__ re,
    const float* __restrict__ im,
    float* __restrict__ out)
{
    extern __shared__ float smem_raw[];
    float2* bufA = (float2*)smem_raw;        // NG buffers of BUFSZ float2
    float2* bufB = bufA + NG * BUFSZ;

    const int tid = threadIdx.x;
    const int grp = tid >> 6;       // which FFT of the 4
    const int t   = tid & 63;       // lane within the 64-thread FFT

    const int b = blockIdx.y;
    const int x = blockIdx.x;       // 0..63: owns frames [16x,16x+16), out [4096x, +4096)

    float2* A = bufA + grp * BUFSZ;
    float2* B = bufB + grp * BUFSZ;

    // loop-invariant twiddles (no smem table)
    float2 w1a, w1b, wp0;
    sincospif(t * (1.0f / 256.0f), &w1a.y, &w1a.x);            // W_512^t   (also stage2 window start)
    sincospif((t >> 3) * (1.0f / 32.0f), &w1b.y, &w1b.x);      // W_512^{8g}
    sincospif(t * (1.0f / 512.0f), &wp0.y, &wp0.x);            // W_1024^t  (pack start)

    const float STC = 0.92387953251128676f;   // cos(pi/8)   pack step
    const float STS = 0.38268343236508977f;   // sin(pi/8)
    const float R45 = 0.70710678118654752f;   // window step: rotate pi/4
    const float CD  = 0.99998117528260111f;   // cos(pi/512)
    const float SD  = 0.00613588464915448f;   // sin(pi/512)

    const int r = tid >> 6;         // output row of this thread (0..3)
    float4 cr = make_float4(0.f, 0.f, 0.f, 0.f);   // 768-sample carry (tid<192 lanes)
    float4* o4 = (float4*)(out + (size_t)b * OUTLEN + (size_t)x * BLK);

    #pragma unroll 1
    for (int q = 0; q < 4; q++) {
        const int f = 16 * x + 4 * q + grp;   // always a valid, uniquely-owned frame

        // ---- fused pack + stage 0 (s=1) in registers; write A in P1 layout ----
        {
            const float* rp = re + ((size_t)b * NFRAMES + f) * BINS;
            const float* ip = im + ((size_t)b * NFRAMES + f) * BINS;
            float2 wp = wp0;
            float2 xr8[8], y[8];
            #pragma unroll
            for (int j = 0; j < 8; j++) {
                int k = t + j * 64;
                float xr = rp[k],       xi = ip[k];
                float yr = rp[512 - k], yi = ip[512 - k];
                if (k == 0) { xi = 0.0f; yi = 0.0f; }  // irfft ignores Im(DC), Im(Nyquist)
                float Er  = 0.5f * (xr + yr), Ei  = 0.5f * (xi - yi);
                float Odr = 0.5f * (xr - yr), Odi = 0.5f * (xi + yi);
                float Ox = Odr * wp.x - Odi * wp.y;
                float Oy = Odr * wp.y + Odi * wp.x;
                xr8[j] = make_float2(Er - Oy, Ei + Ox);
                wp = make_float2(wp.x * STC - wp.y * STS, wp.x * STS + wp.y * STC);
            }
            bfly8_inv(xr8, y);
            int db = 9 * t;                     // P1(8t + k) = 9t + k
            A[db] = y[0];
            float2 wk = w1a;
            A[db + 1] = cmul(y[1], wk); wk = cmul(wk, w1a);
            A[db + 2] = cmul(y[2], wk); wk = cmul(wk, w1a);
            A[db + 3] = cmul(y[3], wk); wk = cmul(wk, w1a);
            A[db + 4] = cmul(y[4], wk); wk = cmul(wk, w1a);
            A[db + 5] = cmul(y[5], wk); wk = cmul(wk, w1a);
            A[db + 6] = cmul(y[6], wk); wk = cmul(wk, w1a);
            A[db + 7] = cmul(y[7], wk);
        }
        __syncthreads();

        // ---- stage 1 (s=8): read A (P1), write B (P2) ----
        {
            float2 xx[8], y[8];
            #pragma unroll
            for (int j = 0; j < 8; j++) xx[j] = A[P1(t + j * 64)];
            bfly8_inv(xx, y);
            const int g = t >> 3, rr = t & 7;
            int db = 72 * g + rr;               // P2(64g + rr + 8k) = 72g + rr + 8k
            B[db] = y[0];
            float2 wk = w1b;
            B[db +  8] = cmul(y[1], wk); wk = cmul(wk, w1b);
            B[db + 16] = cmul(y[2], wk); wk = cmul(wk, w1b);
            B[db + 24] = cmul(y[3], wk); wk = cmul(wk, w1b);
            B[db + 32] = cmul(y[4], wk); wk = cmul(wk, w1b);
            B[db + 40] = cmul(y[5], wk); wk = cmul(wk, w1b);
            B[db + 48] = cmul(y[6], wk); wk = cmul(wk, w1b);
            B[db + 56] = cmul(y[7], wk);
        }
        __syncthreads();

        // ---- stage 2 (s=64, twiddle=1): read B (P2), window+scale, write A linear ----
        {
            float2 xx[8], y[8];
            #pragma unroll
            for (int j = 0; j < 8; j++) xx[j] = B[t + 72 * j];  // P2(t + 64j)
            bfly8_inv(xx, y);
            float2 w = w1a;                     // (cos,sin)(pi*t/256)
            #pragma unroll
            for (int k = 0; k < 8; k++) {
                int m = t + 64 * k;             // z[m] = samples 2m (re), 2m+1 (im)
                float w0  = (0.5f - 0.5f * w.x) * (1.0f / 512.0f);
                float c1  = w.x * CD - w.y * SD;               // cos at sample 2m+1
                float w1w = (0.5f - 0.5f * c1) * (1.0f / 512.0f);
                A[m] = make_float2(y[k].x * w0, y[k].y * w1w);
                w = make_float2(R45 * (w.x - w.y), R45 * (w.x + w.y));  // advance pi/4
            }
        }
        __syncthreads();

        // ---- finalize 1024 samples to gmem + compute register carry ----
        {
            const float4* bf4 = (const float4*)bufA;        // group c stride = 288 float4
            float4 v = cr;                                  // zero for r==3 lanes by invariant
            #pragma unroll
            for (int c = 0; c < 4; c++) {
                if (c <= r) {                               // warp-uniform (rows = 2 warps)
                    float4 wv = bf4[c * 288 + tid - 64 * c];
                    v.x += wv.x; v.y += wv.y; v.z += wv.z; v.w += wv.w;
                }
            }
            o4[(q << 8) + tid] = v;
            float4 nc = make_float4(0.f, 0.f, 0.f, 0.f);
            if (tid < 192) {
                #pragma unroll
                for (int c = 1; c < 4; c++) {
                    if (c > r) {                            // warp-uniform
                        float4 wv = bf4[c * 288 + 256 + tid - 64 * c];
                        nc.x += wv.x; nc.y += wv.y; nc.z += wv.z; nc.w += wv.w;
                    }
                }
            }
            cr = nc;
        }
        __syncthreads();                                    // buffers consumed; safe to refill
    }

    // ---- final carry = tail strip [4096, 4864) ----
    if (tid < TAIL / 4)
        ((float4*)g_strip + (b * NCTAX + x) * (TAIL / 4))[tid] = cr;
}

// add tail strips into the next block's head; x=63 strip is the final 768 samples.
#define K2_JOBS   (NB * NCTAX * (TAIL / 4))      // 196608 float4 jobs
#define K2_UNROLL 4
#define K2_CTAS   (K2_JOBS / (256 * K2_UNROLL))  // 192
#define K2_T      (K2_CTAS * 256)                // 49152 threads

__global__ void __launch_bounds__(256) istft_k2(float* __restrict__ out)
{
    const int tid0 = blockIdx.x * 256 + threadIdx.x;
    const float4* s4 = (const float4*)g_strip;

    float4  s[K2_UNROLL];
    float4* op[K2_UNROLL];
    bool    lastx[K2_UNROLL];

    #pragma unroll
    for (int k = 0; k < K2_UNROLL; k++) {          // batch all strip loads (MLP)
        int gid = tid0 + k * K2_T;
        int b   = gid / (NCTAX * (TAIL / 4));
        int rem = gid - b * (NCTAX * (TAIL / 4));
        int x   = rem / (TAIL / 4);
        int u   = rem - x * (TAIL / 4);
        s[k]     = s4[gid];
        op[k]    = (float4*)(out + (size_t)b * OUTLEN + (size_t)(x + 1) * BLK) + u;
        lastx[k] = (x == NCTAX - 1);
    }
    float4 o[K2_UNROLL];
    #pragma unroll
    for (int k = 0; k < K2_UNROLL; k++)            // batch all out loads (MLP)
        o[k] = lastx[k] ? make_float4(0.f, 0.f, 0.f, 0.f) : *op[k];
    #pragma unroll
    for (int k = 0; k < K2_UNROLL; k++)
        *op[k] = make_float4(o[k].x + s[k].x, o[k].y + s[k].y,
                             o[k].z + s[k].z, o[k].w + s[k].w);
}

extern "C" void kernel_launch(void* const* d_in, const int* in_sizes, int n_in,
                              void* d_out, int out_size) {
    const float* re = (const float*)d_in[0];   // stft_real [16,1024,513]
    const float* im = (const float*)d_in[1];   // stft_imag [16,1024,513]
    float* out = (float*)d_out;                // [16, 262912]

    cudaFuncSetAttribute(istft_k1, cudaFuncAttributeMaxDynamicSharedMemorySize, SMEM_BYTES);
    dim3 grid(NCTAX, NB);
    istft_k1<<<grid, 256, SMEM_BYTES>>>(re, im, out);
    istft_k2<<<K2_CTAS, 256>>>(out);
}

// round 16
// speedup vs baseline: 1.0611x; 1.0611x over previous
#include <cuda_runtime.h>

#define NB       16
#define NFRAMES  1024
#define BINS     513
#define WINL     1024
#define HOP      256
#define OUTLEN   262912                  // (1024-1)*256 + 1024 = 64*4096 + 768
#define BLK      4096                    // core output samples per CTA
#define TAIL     768                     // tail spill samples per CTA
#define NCTAX    64                      // CTAs per batch row
#define NG       4                       // FFTs (frames) per CTA iteration
#define BUFSZ    576                     // padded float2 slots per FFT buffer (=288 float4)

// smem: bufA[NG][576] f2 | bufB[NG][576] f2 = 36KB -> 4 CTAs/SM
#define SMEM_BYTES (2*NG*BUFSZ*8)

// group-scoped barrier: 64 threads (2 warps), ids 1..4
#define GROUP_BAR(g) asm volatile("bar.sync %0, 64;" :: "r"((g) + 1) : "memory")

// tail-spill strips: [batch][ctaX][768]  (static device scratch, 3.1MB)
__device__ float g_strip[NB * NCTAX * TAIL];

__device__ __forceinline__ float2 cmul(float2 a, float2 b) {
    return make_float2(a.x*b.x - a.y*b.y, a.x*b.y + a.y*b.x);
}
__device__ __forceinline__ float2 cadd(float2 a, float2 b){ return make_float2(a.x+b.x, a.y+b.y); }
__device__ __forceinline__ float2 csub(float2 a, float2 b){ return make_float2(a.x-b.x, a.y-b.y); }

// padded layouts (bank-conflict-free for this stage schedule)
__device__ __forceinline__ int P1(int e){ return e + (e >> 3); }        // max 574 < 576
__device__ __forceinline__ int P2(int e){ return e + ((e >> 6) << 3); } // max 567 < 576

// inverse radix-8 butterfly: y_k = sum_j x_j * e^{+2*pi*i*j*k/8}
__device__ __forceinline__ void bfly8_inv(const float2* x, float2* y) {
    float2 apc = cadd(x[0], x[4]), amc = csub(x[0], x[4]);
    float2 bpd = cadd(x[2], x[6]), bmd = csub(x[2], x[6]);
    float2 ib  = make_float2(-bmd.y, bmd.x);
    float2 A0 = cadd(apc, bpd), A2 = csub(apc, bpd);
    float2 A1 = cadd(amc, ib),  A3 = csub(amc, ib);
    float2 cpc = cadd(x[1], x[5]), cmc = csub(x[1], x[5]);
    float2 dpd = cadd(x[3], x[7]), dmd = csub(x[3], x[7]);
    float2 id  = make_float2(-dmd.y, dmd.x);
    float2 B0 = cadd(cpc, dpd), B2 = csub(cpc, dpd);
    float2 B1 = cadd(cmc, id),  B3 = csub(cmc, id);
    const float r = 0.70710678118654752f;
    float2 wB1  = make_float2(r*(B1.x - B1.y),  r*(B1.x + B1.y));   // w8^1 * B1
    float2 iB2  = make_float2(-B2.y, B2.x);                          // w8^2 * B2
    float2 w3B3 = make_float2(-r*(B3.x + B3.y), r*(B3.x - B3.y));   // w8^3 * B3
    y[0] = cadd(A0, B0);   y[4] = csub(A0, B0);
    y[1] = cadd(A1, wB1);  y[5] = csub(A1, wB1);
    y[2] = cadd(A2, iB2);  y[6] = csub(A2, iB2);
    y[3] = cadd(A3, w3B3); y[7] = csub(A3, w3B3);
}

__global__ void __launch_bounds__(256, 4) istft_k1(
    const float* __restrict__ re,
    const float* __restrict__ im,
    float* __restrict__ out)
{
    extern __shared__ float smem_raw[];
    float2* bufA = (float2*)smem_raw;        // NG buffers of BUFSZ float2
    float2* bufB = bufA + NG * BUFSZ;

    const int tid = threadIdx.x;
    const int grp = tid >> 6;       // which FFT of the 4
    const int t   = tid & 63;       // lane within the 64-thread FFT

    const int b = blockIdx.y;
    const int x = blockIdx.x;       // 0..63: owns frames [16x,16x+16), out [4096x, +4096)

    float2* A = bufA + grp * BUFSZ;
    float2* B = bufB + grp * BUFSZ;

    // loop-invariant twiddles (no smem table)
    float2 w1a, w1b, wp0;
    sincospif(t * (1.0f / 256.0f), &w1a.y, &w1a.x);            // W_512^t   (also stage2 window start)
    sincospif((t >> 3) * (1.0f / 32.0f), &w1b.y, &w1b.x);      // W_512^{8g}
    sincospif(t * (1.0f / 512.0f), &wp0.y, &wp0.x);            // W_1024^t  (pack start)

    const float STC = 0.92387953251128676f;   // cos(pi/8)   pack step
    const float STS = 0.38268343236508977f;   // sin(pi/8)
    const float R45 = 0.70710678118654752f;   // window step: rotate pi/4
    const float CD  = 0.99998117528260111f;   // cos(pi/512)
    const float SD  = 0.00613588464915448f;   // sin(pi/512)

    const int r = tid >> 6;         // output row of this thread (0..3)
    float4 cr = make_float4(0.f, 0.f, 0.f, 0.f);   // 768-sample carry (tid<192 lanes)
    float4* o4 = (float4*)(out + (size_t)b * OUTLEN + (size_t)x * BLK);

    #pragma unroll 1
    for (int q = 0; q < 4; q++) {
        const int f = 16 * x + 4 * q + grp;   // always a valid, uniquely-owned frame

        // ---- fused pack + stage 0 (s=1) in registers; write A in P1 layout ----
        {
            const float* rp = re + ((size_t)b * NFRAMES + f) * BINS;
            const float* ip = im + ((size_t)b * NFRAMES + f) * BINS;
            float2 wp = wp0;
            float2 xr8[8], y[8];
            #pragma unroll
            for (int j = 0; j < 8; j++) {
                int k = t + j * 64;
                float xr = rp[k],       xi = ip[k];
                float yr = rp[512 - k], yi = ip[512 - k];
                if (k == 0) { xi = 0.0f; yi = 0.0f; }  // irfft ignores Im(DC), Im(Nyquist)
                float Er  = 0.5f * (xr + yr), Ei  = 0.5f * (xi - yi);
                float Odr = 0.5f * (xr - yr), Odi = 0.5f * (xi + yi);
                float Ox = Odr * wp.x - Odi * wp.y;
                float Oy = Odr * wp.y + Odi * wp.x;
                xr8[j] = make_float2(Er - Oy, Ei + Ox);
                wp = make_float2(wp.x * STC - wp.y * STS, wp.x * STS + wp.y * STC);
            }
            bfly8_inv(xr8, y);
            int db = 9 * t;                     // P1(8t + k) = 9t + k
            A[db] = y[0];
            float2 wk = w1a;
            A[db + 1] = cmul(y[1], wk); wk = cmul(wk, w1a);
            A[db + 2] = cmul(y[2], wk); wk = cmul(wk, w1a);
            A[db + 3] = cmul(y[3], wk); wk = cmul(wk, w1a);
            A[db + 4] = cmul(y[4], wk); wk = cmul(wk, w1a);
            A[db + 5] = cmul(y[5], wk); wk = cmul(wk, w1a);
            A[db + 6] = cmul(y[6], wk); wk = cmul(wk, w1a);
            A[db + 7] = cmul(y[7], wk);
        }
        GROUP_BAR(grp);   // only this group's 2 warps touch A_g between here and stage1

        // ---- stage 1 (s=8): read A (P1), write B (P2) ----
        {
            float2 xx[8], y[8];
            #pragma unroll
            for (int j = 0; j < 8; j++) xx[j] = A[P1(t + j * 64)];
            bfly8_inv(xx, y);
            const int g = t >> 3, rr = t & 7;
            int db = 72 * g + rr;               // P2(64g + rr + 8k) = 72g + rr + 8k
            B[db] = y[0];
            float2 wk = w1b;
            B[db +  8] = cmul(y[1], wk); wk = cmul(wk, w1b);
            B[db + 16] = cmul(y[2], wk); wk = cmul(wk, w1b);
            B[db + 24] = cmul(y[3], wk); wk = cmul(wk, w1b);
            B[db + 32] = cmul(y[4], wk); wk = cmul(wk, w1b);
            B[db + 40] = cmul(y[5], wk); wk = cmul(wk, w1b);
            B[db + 48] = cmul(y[6], wk); wk = cmul(wk, w1b);
            B[db + 56] = cmul(y[7], wk);
        }
        GROUP_BAR(grp);   // B_g produced/consumed only within group g

        // ---- stage 2 (s=64, twiddle=1): read B (P2), window+scale, write A linear ----
        {
            float2 xx[8], y[8];
            #pragma unroll
            for (int j = 0; j < 8; j++) xx[j] = B[t + 72 * j];  // P2(t + 64j)
            bfly8_inv(xx, y);
            float2 w = w1a;                     // (cos,sin)(pi*t/256)
            #pragma unroll
            for (int k = 0; k < 8; k++) {
                int m = t + 64 * k;             // z[m] = samples 2m (re), 2m+1 (im)
                float w0  = (0.5f - 0.5f * w.x) * (1.0f / 512.0f);
                float c1  = w.x * CD - w.y * SD;               // cos at sample 2m+1
                float w1w = (0.5f - 0.5f * c1) * (1.0f / 512.0f);
                A[m] = make_float2(y[k].x * w0, y[k].y * w1w);
                w = make_float2(R45 * (w.x - w.y), R45 * (w.x + w.y));  // advance pi/4
            }
        }
        __syncthreads();   // finalize reads ALL groups' A -> full-CTA scope required

        // ---- finalize 1024 samples to gmem + compute register carry ----
        {
            const float4* bf4 = (const float4*)bufA;        // group c stride = 288 float4
            float4 v = cr;                                  // zero for r==3 lanes by invariant
            #pragma unroll
            for (int c = 0; c < 4; c++) {
                if (c <= r) {                               // warp-uniform (rows = 2 warps)
                    float4 wv = bf4[c * 288 + tid - 64 * c];
                    v.x += wv.x; v.y += wv.y; v.z += wv.z; v.w += wv.w;
                }
            }
            o4[(q << 8) + tid] = v;
            float4 nc = make_float4(0.f, 0.f, 0.f, 0.f);
            if (tid < 192) {
                #pragma unroll
                for (int c = 1; c < 4; c++) {
                    if (c > r) {                            // warp-uniform
                        float4 wv = bf4[c * 288 + 256 + tid - 64 * c];
                        nc.x += wv.x; nc.y += wv.y; nc.z += wv.z; nc.w += wv.w;
                    }
                }
            }
            cr = nc;
        }
        __syncthreads();   // next pack overwrites A buffers that finalize read -> full scope
    }

    // ---- final carry = tail strip [4096, 4864) ----
    if (tid < TAIL / 4)
        ((float4*)g_strip + (b * NCTAX + x) * (TAIL / 4))[tid] = cr;
}

// add tail strips into the next block's head; x=63 strip is the final 768 samples.
#define K2_JOBS   (NB * NCTAX * (TAIL / 4))      // 196608 float4 jobs
#define K2_UNROLL 4
#define K2_CTAS   (K2_JOBS / (256 * K2_UNROLL))  // 192
#define K2_T      (K2_CTAS * 256)                // 49152 threads

__global__ void __launch_bounds__(256) istft_k2(float* __restrict__ out)
{
    const int tid0 = blockIdx.x * 256 + threadIdx.x;
    const float4* s4 = (const float4*)g_strip;

    float4  s[K2_UNROLL];
    float4* op[K2_UNROLL];
    bool    lastx[K2_UNROLL];

    #pragma unroll
    for (int k = 0; k < K2_UNROLL; k++) {          // batch all strip loads (MLP)
        int gid = tid0 + k * K2_T;
        int b   = gid / (NCTAX * (TAIL / 4));
        int rem = gid - b * (NCTAX * (TAIL / 4));
        int x   = rem / (TAIL / 4);
        int u   = rem - x * (TAIL / 4);
        s[k]     = s4[gid];
        op[k]    = (float4*)(out + (size_t)b * OUTLEN + (size_t)(x + 1) * BLK) + u;
        lastx[k] = (x == NCTAX - 1);
    }
    float4 o[K2_UNROLL];
    #pragma unroll
    for (int k = 0; k < K2_UNROLL; k++)            // batch all out loads (MLP)
        o[k] = lastx[k] ? make_float4(0.f, 0.f, 0.f, 0.f) : *op[k];
    #pragma unroll
    for (int k = 0; k < K2_UNROLL; k++)
        *op[k] = make_float4(o[k].x + s[k].x, o[k].y + s[k].y,
                             o[k].z + s[k].z, o[k].w + s[k].w);
}

extern "C" void kernel_launch(void* const* d_in, const int* in_sizes, int n_in,
                              void* d_out, int out_size) {
    const float* re = (const float*)d_in[0];   // stft_real [16,1024,513]
    const float* im = (const float*)d_in[1];   // stft_imag [16,1024,513]
    float* out = (float*)d_out;                // [16, 262912]

    cudaFuncSetAttribute(istft_k1, cudaFuncAttributeMaxDynamicSharedMemorySize, SMEM_BYTES);
    dim3 grid(NCTAX, NB);
    istft_k1<<<grid, 256, SMEM_BYTES>>>(re, im, out);
    istft_k2<<<K2_CTAS, 256>>>(out);
}